// round 3
// baseline (speedup 1.0000x reference)
#include <cuda_runtime.h>
#include <math.h>
#include <stdint.h>

// ---------------- problem constants ----------------
#define PB 32
#define PT 512
#define PD 512
#define PH 8
#define PK 64
#define PDH 64
#define ROWS (PB*PT)           // 16384

// ---------------- scratch (device globals; no allocation) ----------------
__device__ float  g_nx  [ROWS*PD];
__device__ float  g_nkv [ROWS*PD];
__device__ float  g_q   [ROWS*PD];
__device__ float  g_k   [ROWS*PD];
__device__ float  g_v   [ROWS*PD];
__device__ float  g_o   [ROWS*PD];
__device__ float  g_h1  [ROWS*PD];
__device__ float  g_nh1 [ROWS*PD];
__device__ float  g_gv  [ROWS*4096];
__device__ float  g_u   [ROWS*2048];
__device__ double g_qwin[PB*PD];
__device__ float  g_read[PB*PD];

// ---------------- RMSNorm: one row per block, optional 2nd output ----------------
__global__ void rmsnorm_kernel(const float* __restrict__ x,
                               const float* __restrict__ s1, float* __restrict__ o1,
                               const float* __restrict__ s2, float* __restrict__ o2)
{
    int row = blockIdx.x, tid = threadIdx.x;        // 256 threads, 2 elems each
    const float* xr = x + (size_t)row * PD;
    float v0 = xr[tid], v1 = xr[tid + 256];
    __shared__ float sred[256];
    sred[tid] = v0*v0 + v1*v1;
    __syncthreads();
    for (int s = 128; s >= 1; s >>= 1) {
        if (tid < s) sred[tid] += sred[tid + s];
        __syncthreads();
    }
    float inv = rsqrtf(sred[0] * (1.0f/512.0f) + 1e-6f);
    size_t base = (size_t)row * PD;
    o1[base + tid]       = v0 * inv * s1[tid];
    o1[base + tid + 256] = v1 * inv * s1[tid + 256];
    if (o2) {
        o2[base + tid]       = v0 * inv * s2[tid];
        o2[base + tid + 256] = v1 * inv * s2[tid + 256];
    }
}

// ---------------- SGEMM: 128x128 tile, BK=16, 256 threads, 8x8 microtile ----------------
template<bool BIAS, bool RES>
__global__ void __launch_bounds__(256) sgemm_kernel(
    const float* __restrict__ A, const float* __restrict__ Bm,
    const float* __restrict__ bias, const float* __restrict__ res,
    float* __restrict__ C, int M, int N, int Kd)
{
    __shared__ float As[16][128];
    __shared__ float Bs[16][128];
    int tid = threadIdx.x;
    int row0 = blockIdx.y * 128, col0 = blockIdx.x * 128;
    int ty = tid >> 4, tx = tid & 15;
    float acc[8][8];
#pragma unroll
    for (int i = 0; i < 8; i++)
#pragma unroll
        for (int j = 0; j < 8; j++) acc[i][j] = 0.0f;

    int ar = tid >> 2;            // 0..63
    int ac = (tid & 3) << 2;      // 0,4,8,12
    int br = tid >> 5;            // 0..7
    int bc = (tid & 31) << 2;     // 0..124

    for (int k0 = 0; k0 < Kd; k0 += 16) {
        float4 a0 = *(const float4*)&A[(size_t)(row0 + ar)      * Kd + k0 + ac];
        float4 a1 = *(const float4*)&A[(size_t)(row0 + ar + 64) * Kd + k0 + ac];
        float4 b0 = *(const float4*)&Bm[(size_t)(k0 + br)     * N + col0 + bc];
        float4 b1 = *(const float4*)&Bm[(size_t)(k0 + br + 8) * N + col0 + bc];
        As[ac+0][ar] = a0.x; As[ac+1][ar] = a0.y; As[ac+2][ar] = a0.z; As[ac+3][ar] = a0.w;
        As[ac+0][ar+64] = a1.x; As[ac+1][ar+64] = a1.y; As[ac+2][ar+64] = a1.z; As[ac+3][ar+64] = a1.w;
        *(float4*)&Bs[br][bc]     = b0;
        *(float4*)&Bs[br + 8][bc] = b1;
        __syncthreads();
#pragma unroll
        for (int kk = 0; kk < 16; kk++) {
            float av[8], bv[8];
#pragma unroll
            for (int i = 0; i < 8; i++) av[i] = As[kk][ty*8 + i];
#pragma unroll
            for (int j = 0; j < 8; j++) bv[j] = Bs[kk][tx*8 + j];
#pragma unroll
            for (int i = 0; i < 8; i++)
#pragma unroll
                for (int j = 0; j < 8; j++) acc[i][j] = fmaf(av[i], bv[j], acc[i][j]);
        }
        __syncthreads();
    }
#pragma unroll
    for (int i = 0; i < 8; i++) {
        int r = row0 + ty*8 + i;
#pragma unroll
        for (int j = 0; j < 8; j++) {
            int c = col0 + tx*8 + j;
            float vv = acc[i][j];
            if (BIAS) vv += bias[c];
            if (RES)  vv += res[(size_t)r * N + c];
            C[(size_t)r * N + c] = vv;
        }
    }
}

// ---------------- RoPE (in place on q and k) ----------------
__global__ void rope_kernel(float* __restrict__ q, float* __restrict__ k)
{
    int idx = blockIdx.x * blockDim.x + threadIdx.x;
    int row = idx >> 8;
    int p   = idx & 255;          // pair index across heads; col = 2*p
    int i   = p & 31;             // pair within head (DH/2 = 32)
    int t   = row & (PT - 1);
    // high-accuracy freq and angle (double), rotation applied in f32
    double freq = exp(-((double)(2*i) / 64.0) * 9.210340371976184);  // 10000^(-2i/64)
    double ang = (double)t * freq;
    float cs = (float)cos(ang);
    float sn = (float)sin(ang);
    size_t off = (size_t)row * PD + 2*p;
    float x0 = q[off], x1 = q[off+1];
    q[off]   = x0*cs - x1*sn;
    q[off+1] = x0*sn + x1*cs;
    x0 = k[off]; x1 = k[off+1];
    k[off]   = x0*cs - x1*sn;
    k[off+1] = x0*sn + x1*cs;
}

// ---------------- causal attention: 1 thread = 1 query row, 32-key tiles ----------------
__global__ void __launch_bounds__(128) attn_kernel(
    const float* __restrict__ q, const float* __restrict__ k,
    const float* __restrict__ v, float* __restrict__ o)
{
    const int BS = 32;
    __shared__ float Ks[BS][64];
    __shared__ float Vs[BS][64];
    int t = blockIdx.x * 128 + threadIdx.x;
    int h = blockIdx.y, b = blockIdx.z;
    const float* qrow = q + ((size_t)(b*PT + t) * PD + h*PDH);
    float qreg[64];
#pragma unroll
    for (int i = 0; i < 64; i++) qreg[i] = qrow[i];
    float m = -1e30f, l = 0.0f;
    float acc[64];
#pragma unroll
    for (int i = 0; i < 64; i++) acc[i] = 0.0f;

    int send = blockIdx.x * 128 + 128;
    for (int s0 = 0; s0 < send; s0 += BS) {
        __syncthreads();
        for (int i = threadIdx.x; i < BS*64/4; i += 128) {
            int rr = i >> 4; int cc = (i & 15) << 2;
            size_t goff = (size_t)(b*PT + s0 + rr) * PD + h*PDH + cc;
            *(float4*)&Ks[rr][cc] = *(const float4*)&k[goff];
            *(float4*)&Vs[rr][cc] = *(const float4*)&v[goff];
        }
        __syncthreads();
        int nval = t - s0 + 1;
        if (nval > BS) nval = BS;
        if (nval > 0) {
            float sc[BS];
            float tm = -1e30f;
#pragma unroll
            for (int j = 0; j < BS; j++) {
                float s = 0.0f;
#pragma unroll
                for (int d = 0; d < 64; d++) s = fmaf(qreg[d], Ks[j][d], s);
                s *= 0.125f;
                sc[j] = (j < nval) ? s : -1e30f;
                tm = fmaxf(tm, sc[j]);
            }
            float nm = fmaxf(m, tm);
            float csc = expf(m - nm);
            l *= csc;
#pragma unroll
            for (int d = 0; d < 64; d++) acc[d] *= csc;
#pragma unroll
            for (int j = 0; j < BS; j++) {
                float p = expf(sc[j] - nm);
                l += p;
#pragma unroll
                for (int d = 0; d < 64; d++) acc[d] = fmaf(p, Vs[j][d], acc[d]);
            }
            m = nm;
        }
    }
    float inv = 1.0f / l;
    float* orow = o + ((size_t)(b*PT + t) * PD + h*PDH);
#pragma unroll
    for (int i = 0; i < 64; i++) orow[i] = acc[i] * inv;
}

// ---------------- silu(g) * val ----------------
__global__ void silu_mul_kernel(const float* __restrict__ gv, float* __restrict__ u)
{
    size_t idx = (size_t)blockIdx.x * blockDim.x + threadIdx.x;  // 16384*2048
    size_t row = idx >> 11;
    int c = (int)(idx & 2047);
    float g  = gv[row*4096 + c];
    float vl = gv[row*4096 + 2048 + c];
    u[idx] = g / (1.0f + expf(-g)) * vl;
}

// ---------------- mean over T (float64 accumulation) ----------------
__global__ void qwin_kernel(const float* __restrict__ h2, double* __restrict__ qwin)
{
    int b = blockIdx.x, d = threadIdx.x;   // 512 threads
    double s = 0.0;
    for (int t = 0; t < PT; t++) s += (double)h2[((size_t)(b*PT + t)) * PD + d];
    qwin[b*PD + d] = s * (1.0 / (double)PT);
}

// ---------------- episodic memory (float64 internals): one block per batch ----------------
__global__ void __launch_bounds__(512) episodic_kernel(
    const float* __restrict__ epi_keys, const float* __restrict__ epi_vals,
    const float* __restrict__ epi_age,  const float* __restrict__ epi_str,
    const float* __restrict__ rms_read,
    const float* __restrict__ Wwk, const float* __restrict__ bwk,
    const float* __restrict__ Wwv, const float* __restrict__ bwv,
    const float* __restrict__ Wws, const float* __restrict__ bws,
    const float* __restrict__ Wg1, const float* __restrict__ bg1,
    const float* __restrict__ Wg2, const float* __restrict__ bg2,
    const double* __restrict__ qwin,
    float* __restrict__ read_out,
    float* __restrict__ keys_new, float* __restrict__ vals_new,
    float* __restrict__ age_new,  float* __restrict__ sn_out,
    float* __restrict__ gate_out)
{
    int b = blockIdx.x;
    int tid = threadIdx.x;          // 512
    int warp = tid >> 5, lane = tid & 31;
    __shared__ double qw[512], wk[512], wv[512], sred[512];
    __shared__ double lg[64], sw[64], wr[64];
    __shared__ double s_qninv, s_ws, s_wkinv, s_best;
    __shared__ int    s_kstar;

    qw[tid] = qwin[b*PD + tid];
    __syncthreads();

    // ||q_win||
    sred[tid] = qw[tid]*qw[tid];
    __syncthreads();
    for (int s = 256; s >= 1; s >>= 1) { if (tid < s) sred[tid] += sred[tid+s]; __syncthreads(); }
    if (tid == 0) s_qninv = 1.0 / (sqrt(sred[0]) + 1e-6);
    __syncthreads();

    // write_key / write_val matvecs (f64)
    double a1 = 0.0, a2 = 0.0;
    for (int i = 0; i < 512; i++) {
        double qv = qw[i];
        a1 += qv * (double)Wwk[i*512 + tid];
        a2 += qv * (double)Wwv[i*512 + tid];
    }
    wk[tid] = a1 + (double)bwk[tid];
    wv[tid] = a2 + (double)bwv[tid];

    // ws = sigmoid(q_win . Wws + bws)
    sred[tid] = qw[tid] * (double)Wws[tid];
    __syncthreads();
    for (int s = 256; s >= 1; s >>= 1) { if (tid < s) sred[tid] += sred[tid+s]; __syncthreads(); }
    if (tid == 0) s_ws = 1.0 / (1.0 + exp(-(sred[0] + (double)bws[0])));
    __syncthreads();

    // ||write_key||
    sred[tid] = wk[tid]*wk[tid];
    __syncthreads();
    for (int s = 256; s >= 1; s >>= 1) { if (tid < s) sred[tid] += sred[tid+s]; __syncthreads(); }
    if (tid == 0) s_wkinv = 1.0 / (sqrt(sred[0]) + 1e-6);
    __syncthreads();

    // per-slot similarities (f64): one warp per slot
    for (int kk = warp; kk < PK; kk += 16) {
        const float* kp = epi_keys + (size_t)(b*PK + kk) * PD;
        double ss = 0.0, dq = 0.0, dw = 0.0;
        for (int d = lane; d < 512; d += 32) {
            double kv = (double)kp[d];
            ss += kv * kv;
            dq += kv * qw[d];
            dw += kv * wk[d];
        }
#pragma unroll
        for (int o = 16; o > 0; o >>= 1) {
            ss += __shfl_xor_sync(0xffffffffu, ss, o);
            dq += __shfl_xor_sync(0xffffffffu, dq, o);
            dw += __shfl_xor_sync(0xffffffffu, dw, o);
        }
        if (lane == 0) {
            double kninv = 1.0 / (sqrt(ss) + 1e-6);
            double simr  = dq * kninv * s_qninv;
            double st    = (double)epi_str[b*PK + kk];
            double stc   = fmin(fmax(st, 0.001), 1e9);
            lg[kk] = simr + 0.5*log(stc) - 0.02*(double)epi_age[b*PK + kk]
                   + ((st > 0.001) ? 0.0 : -1000.0);
            sw[kk] = dw * kninv * s_wkinv;
        }
    }
    __syncthreads();

    // softmax over 64 logits + argmax(sim_w)   (write_w == one_hot(argmax))
    if (tid == 0) {
        double mx = -1e300;
        for (int kk = 0; kk < PK; kk++) mx = fmax(mx, lg[kk]);
        double sm = 0.0;
        for (int kk = 0; kk < PK; kk++) { double e = exp(lg[kk]-mx); wr[kk] = e; sm += e; }
        double inv = 1.0 / sm;
        for (int kk = 0; kk < PK; kk++) wr[kk] *= inv;
        double bs = -1e300; int kst = 0;
        for (int kk = 0; kk < PK; kk++) if (sw[kk] > bs) { bs = sw[kk]; kst = kk; }
        s_best = bs; s_kstar = kst;
    }
    __syncthreads();

    // read = rms(sum_k w_read * vals)
    double r = 0.0;
    for (int kk = 0; kk < PK; kk++)
        r += wr[kk] * (double)epi_vals[(size_t)(b*PK + kk)*PD + tid];
    sred[tid] = r*r;
    __syncthreads();
    for (int s = 256; s >= 1; s >>= 1) { if (tid < s) sred[tid] += sred[tid+s]; __syncthreads(); }
    double rinv = 1.0 / sqrt(sred[0] * (1.0/512.0) + 1e-6);
    read_out[b*PD + tid] = (float)(r * rinv * (double)rms_read[tid]);
    __syncthreads();

    double ws = s_ws; int kstar = s_kstar;

    // keys_new / vals_new: one warp per slot
    for (int kk = warp; kk < PK; kk += 16) {
        double re = (kk == kstar) ? ws * 0.5 : 0.0;
        const float* kp = epi_keys + (size_t)(b*PK + kk) * PD;
        const float* vp = epi_vals + (size_t)(b*PK + kk) * PD;
        double ss = 0.0;
        for (int d = lane; d < 512; d += 32) {
            double tk = (1.0 - re)*(double)kp[d] + re*wk[d];
            ss += tk * tk;
            vals_new[(size_t)(b*PK + kk)*PD + d] =
                (float)((1.0 - re)*(double)vp[d] + re*wv[d]);
        }
#pragma unroll
        for (int o = 16; o > 0; o >>= 1) ss += __shfl_xor_sync(0xffffffffu, ss, o);
        double ninv = 1.0 / (sqrt(ss) + 1e-6);
        for (int d = lane; d < 512; d += 32) {
            double tk = (1.0 - re)*(double)kp[d] + re*wk[d];
            keys_new[(size_t)(b*PK + kk)*PD + d] = (float)(tk * ninv);
        }
    }

    // age / strength
    if (tid < PK) {
        int kk = tid;
        double ww = (kk == kstar) ? 1.0 : 0.0;
        age_new[b*PK + kk] = (float)(((double)epi_age[b*PK + kk] + 1.0) * (1.0 - ww));
        double s0 = (double)epi_str[b*PK + kk] * 0.995;
        double snv = s0 + ww * ws * (1.0 - s0);
        sn_out[b*PK + kk] = (float)fmin(fmax(snv, 0.001), 1.0);
    }

    // gate MLP: xg = [q_win(512), ws, novelty]  (f64)
    double nov = 1.0 - s_best;
    double hsum = (double)bg1[tid];
    for (int i = 0; i < 512; i++) hsum += qw[i] * (double)Wg1[i*512 + tid];
    hsum += ws  * (double)Wg1[512*512 + tid];
    hsum += nov * (double)Wg1[513*512 + tid];
    double sil = hsum / (1.0 + exp(-hsum));
    sred[tid] = sil * (double)Wg2[tid];
    __syncthreads();
    for (int s = 256; s >= 1; s >>= 1) { if (tid < s) sred[tid] += sred[tid+s]; __syncthreads(); }
    if (tid == 0) gate_out[b] = (float)(1.0 / (1.0 + exp(-(sred[0] + (double)bg2[0]))));
}

// ---------------- out += gate[b] * read[b, :] ----------------
__global__ void bcast_add_kernel(float* __restrict__ out,
                                 const float* __restrict__ read,
                                 const float* __restrict__ gate)
{
    size_t idx = (size_t)blockIdx.x * blockDim.x + threadIdx.x;  // 8388608
    int b = (int)(idx >> 18);         // T*D = 262144 per batch
    int d = (int)(idx & 511);
    out[idx] += gate[b] * read[b*PD + d];
}

// ---------------- launch ----------------
extern "C" void kernel_launch(void* const* d_in, const int* in_sizes, int n_in,
                              void* d_out, int out_size)
{
    const float* x        = (const float*)d_in[0];
    const float* epi_keys = (const float*)d_in[1];
    const float* epi_vals = (const float*)d_in[2];
    const float* epi_age  = (const float*)d_in[3];
    const float* epi_str  = (const float*)d_in[4];
    // d_in[5] = pos_idx (arange, implicit)
    const float* rms1     = (const float*)d_in[6];
    const float* rms_kv   = (const float*)d_in[7];
    const float* rms2     = (const float*)d_in[8];
    const float* rms_read = (const float*)d_in[9];
    const float* Wq = (const float*)d_in[10]; const float* bq = (const float*)d_in[11];
    const float* Wk = (const float*)d_in[12]; const float* bk = (const float*)d_in[13];
    const float* Wv = (const float*)d_in[14]; const float* bv = (const float*)d_in[15];
    const float* Wo = (const float*)d_in[16]; const float* bo = (const float*)d_in[17];
    const float* W1 = (const float*)d_in[18]; const float* W2 = (const float*)d_in[19];
    const float* Wwk = (const float*)d_in[20]; const float* bwk = (const float*)d_in[21];
    const float* Wwv = (const float*)d_in[22]; const float* bwv = (const float*)d_in[23];
    const float* Wws = (const float*)d_in[24]; const float* bws = (const float*)d_in[25];
    const float* Wg1 = (const float*)d_in[26]; const float* bg1 = (const float*)d_in[27];
    const float* Wg2 = (const float*)d_in[28]; const float* bg2 = (const float*)d_in[29];

    float *nx, *nkv, *q, *k, *v, *o, *h1, *nh1, *gv, *u, *readb;
    double *qwin;
    cudaGetSymbolAddress((void**)&nx,   g_nx);
    cudaGetSymbolAddress((void**)&nkv,  g_nkv);
    cudaGetSymbolAddress((void**)&q,    g_q);
    cudaGetSymbolAddress((void**)&k,    g_k);
    cudaGetSymbolAddress((void**)&v,    g_v);
    cudaGetSymbolAddress((void**)&o,    g_o);
    cudaGetSymbolAddress((void**)&h1,   g_h1);
    cudaGetSymbolAddress((void**)&nh1,  g_nh1);
    cudaGetSymbolAddress((void**)&gv,   g_gv);
    cudaGetSymbolAddress((void**)&u,    g_u);
    cudaGetSymbolAddress((void**)&qwin, g_qwin);
    cudaGetSymbolAddress((void**)&readb,g_read);

    float* out      = (float*)d_out;
    float* keys_new = out + (size_t)ROWS*PD;                 // 8388608
    float* vals_new = keys_new + (size_t)PB*PK*PD;           // +1048576
    float* age_new  = vals_new + (size_t)PB*PK*PD;           // +1048576
    float* sn       = age_new + PB*PK;                       // +2048
    float* gate     = sn + PB*PK;                            // +2048

    dim3 blk(256);
    dim3 g512(512/128, ROWS/128);    // (4, 128)
    dim3 g4096(4096/128, ROWS/128);  // (32, 128)

    rmsnorm_kernel<<<ROWS, 256>>>(x, rms1, nx, rms_kv, nkv);
    sgemm_kernel<true,false><<<g512, blk>>>(nx,  Wq, bq, nullptr, q, ROWS, 512, 512);
    sgemm_kernel<true,false><<<g512, blk>>>(nkv, Wk, bk, nullptr, k, ROWS, 512, 512);
    sgemm_kernel<true,false><<<g512, blk>>>(nkv, Wv, bv, nullptr, v, ROWS, 512, 512);
    rope_kernel<<<ROWS, 256>>>(q, k);
    attn_kernel<<<dim3(PT/128, PH, PB), 128>>>(q, k, v, o);
    sgemm_kernel<true,true><<<g512, blk>>>(o, Wo, bo, x, h1, ROWS, 512, 512);
    rmsnorm_kernel<<<ROWS, 256>>>(h1, rms2, nh1, nullptr, nullptr);
    sgemm_kernel<false,false><<<g4096, blk>>>(nh1, W1, nullptr, nullptr, gv, ROWS, 4096, 512);
    silu_mul_kernel<<<(ROWS*2048)/256, 256>>>(gv, u);
    sgemm_kernel<false,true><<<g512, blk>>>(u, W2, nullptr, h1, out, ROWS, 512, 2048);
    qwin_kernel<<<PB, 512>>>(out, qwin);
    episodic_kernel<<<PB, 512>>>(epi_keys, epi_vals, epi_age, epi_str, rms_read,
                                 Wwk, bwk, Wwv, bwv, Wws, bws, Wg1, bg1, Wg2, bg2,
                                 qwin, readb, keys_new, vals_new, age_new, sn, gate);
    bcast_add_kernel<<<(ROWS*PD)/256, 256>>>(out, readb, gate);
}

// round 4
// speedup vs baseline: 1.1590x; 1.1590x over previous
#include <cuda_runtime.h>
#include <math.h>
#include <stdint.h>

// ---------------- problem constants ----------------
#define PB 32
#define PT 512
#define PD 512
#define PH 8
#define PK 64
#define PDH 64
#define ROWS (PB*PT)           // 16384

// ---------------- scratch (device globals; no allocation) ----------------
__device__ float  g_nx  [ROWS*PD];
__device__ float  g_nkv [ROWS*PD];
__device__ float  g_q   [ROWS*PD];
__device__ float  g_k   [ROWS*PD];
__device__ float  g_v   [ROWS*PD];
__device__ float  g_o   [ROWS*PD];
__device__ float  g_h1  [ROWS*PD];
__device__ float  g_nh1 [ROWS*PD];
__device__ float  g_gv  [ROWS*4096];
__device__ float  g_u   [ROWS*2048];
__device__ double g_qwin[PB*PD];
__device__ float  g_read[PB*PD];

// ---------------- tf32 split helpers ----------------
__device__ __forceinline__ void split_tf32(float x, uint32_t &hi, uint32_t &lo) {
    asm("cvt.rna.tf32.f32 %0, %1;" : "=r"(hi) : "f"(x));
    float h = __uint_as_float(hi);
    float r = x - h;
    asm("cvt.rna.tf32.f32 %0, %1;" : "=r"(lo) : "f"(r));
}

__device__ __forceinline__ void mma_tf32(float4 &d,
    uint32_t a0, uint32_t a1, uint32_t a2, uint32_t a3,
    uint32_t b0, uint32_t b1)
{
    asm volatile(
        "mma.sync.aligned.m16n8k8.row.col.f32.tf32.tf32.f32 "
        "{%0,%1,%2,%3}, {%4,%5,%6,%7}, {%8,%9}, {%0,%1,%2,%3};"
        : "+f"(d.x), "+f"(d.y), "+f"(d.z), "+f"(d.w)
        : "r"(a0), "r"(a1), "r"(a2), "r"(a3), "r"(b0), "r"(b1));
}

// ---------------- 3xTF32 tensor-core GEMM ----------------
// C[M,N] = A[M,K] @ B[K,N] (+bias) (+res).  CTA tile 128x128, BK=32,
// 8 warps (4m x 2n), warp tile 32x64, mma m16n8k8, 3 MMAs per product (hi/lo split).
template<bool BIAS, bool RES>
__global__ void __launch_bounds__(256, 1) mma_gemm_kernel(
    const float* __restrict__ A, const float* __restrict__ Bm,
    const float* __restrict__ bias, const float* __restrict__ res,
    float* __restrict__ C, int M, int N, int Kd)
{
    __shared__ float As[128][36];    // [m][k], pad 36 -> conflict-free frag loads
    __shared__ float Bs[32][136];    // [k][n], pad 136 -> conflict-free frag loads
    const int tid  = threadIdx.x;
    const int lane = tid & 31, warp = tid >> 5;
    const int wm = warp >> 1, wn = warp & 1;
    const int row0 = blockIdx.y * 128, col0 = blockIdx.x * 128;

    float4 acc[2][8];
#pragma unroll
    for (int i = 0; i < 2; i++)
#pragma unroll
        for (int j = 0; j < 8; j++) acc[i][j] = make_float4(0.f, 0.f, 0.f, 0.f);

    // global->reg staging mappings (4 float4 per thread for A and B)
    const int a_row = tid >> 1;            // 0..127
    const int a_cb  = (tid & 1) * 16;      // 0 or 16
    const int b_row = tid >> 3;            // 0..31
    const int b_cb  = (tid & 7) * 16;      // 0..112

    float4 pa[4], pb[4];
    const int nk = Kd >> 5;

    // preload k0 = 0
#pragma unroll
    for (int i = 0; i < 4; i++) {
        pa[i] = *(const float4*)&A[(size_t)(row0 + a_row) * Kd + a_cb + 4*i];
        pb[i] = *(const float4*)&Bm[(size_t)(b_row) * N + col0 + b_cb + 4*i];
    }

    for (int it = 0; it < nk; it++) {
#pragma unroll
        for (int i = 0; i < 4; i++) {
            *(float4*)&As[a_row][a_cb + 4*i] = pa[i];
            *(float4*)&Bs[b_row][b_cb + 4*i] = pb[i];
        }
        __syncthreads();

        if (it + 1 < nk) {
            int k0 = (it + 1) << 5;
#pragma unroll
            for (int i = 0; i < 4; i++) {
                pa[i] = *(const float4*)&A[(size_t)(row0 + a_row) * Kd + k0 + a_cb + 4*i];
                pb[i] = *(const float4*)&Bm[(size_t)(k0 + b_row) * N + col0 + b_cb + 4*i];
            }
        }

#pragma unroll
        for (int kk = 0; kk < 4; kk++) {
            const int kb = kk * 8;
            uint32_t ahi[2][4], alo[2][4], bhi[8][2], blo[8][2];
#pragma unroll
            for (int tm = 0; tm < 2; tm++) {
                int r0 = wm*32 + tm*16 + (lane >> 2);
                float x0 = As[r0    ][kb + (lane & 3)];
                float x1 = As[r0 + 8][kb + (lane & 3)];
                float x2 = As[r0    ][kb + 4 + (lane & 3)];
                float x3 = As[r0 + 8][kb + 4 + (lane & 3)];
                split_tf32(x0, ahi[tm][0], alo[tm][0]);
                split_tf32(x1, ahi[tm][1], alo[tm][1]);
                split_tf32(x2, ahi[tm][2], alo[tm][2]);
                split_tf32(x3, ahi[tm][3], alo[tm][3]);
            }
#pragma unroll
            for (int tn = 0; tn < 8; tn++) {
                int c = wn*64 + tn*8 + (lane >> 2);
                float y0 = Bs[kb + (lane & 3)][c];
                float y1 = Bs[kb + 4 + (lane & 3)][c];
                split_tf32(y0, bhi[tn][0], blo[tn][0]);
                split_tf32(y1, bhi[tn][1], blo[tn][1]);
            }
#pragma unroll
            for (int tm = 0; tm < 2; tm++)
#pragma unroll
                for (int tn = 0; tn < 8; tn++) {
                    mma_tf32(acc[tm][tn], ahi[tm][0], ahi[tm][1], ahi[tm][2], ahi[tm][3],
                             bhi[tn][0], bhi[tn][1]);
                    mma_tf32(acc[tm][tn], ahi[tm][0], ahi[tm][1], ahi[tm][2], ahi[tm][3],
                             blo[tn][0], blo[tn][1]);
                    mma_tf32(acc[tm][tn], alo[tm][0], alo[tm][1], alo[tm][2], alo[tm][3],
                             bhi[tn][0], bhi[tn][1]);
                }
        }
        __syncthreads();
    }

    // epilogue
#pragma unroll
    for (int tm = 0; tm < 2; tm++) {
        int r0 = row0 + wm*32 + tm*16 + (lane >> 2);
#pragma unroll
        for (int tn = 0; tn < 8; tn++) {
            int c0 = col0 + wn*64 + tn*8 + 2*(lane & 3);
            float2 v0 = make_float2(acc[tm][tn].x, acc[tm][tn].y);
            float2 v1 = make_float2(acc[tm][tn].z, acc[tm][tn].w);
            if (BIAS) {
                v0.x += bias[c0]; v0.y += bias[c0+1];
                v1.x += bias[c0]; v1.y += bias[c0+1];
            }
            if (RES) {
                float2 r0v = *(const float2*)&res[(size_t)r0 * N + c0];
                float2 r1v = *(const float2*)&res[(size_t)(r0+8) * N + c0];
                v0.x += r0v.x; v0.y += r0v.y;
                v1.x += r1v.x; v1.y += r1v.y;
            }
            *(float2*)&C[(size_t)r0 * N + c0]     = v0;
            *(float2*)&C[(size_t)(r0+8) * N + c0] = v1;
        }
    }
}

// ---------------- RMSNorm: one row per block, optional 2nd output ----------------
__global__ void rmsnorm_kernel(const float* __restrict__ x,
                               const float* __restrict__ s1, float* __restrict__ o1,
                               const float* __restrict__ s2, float* __restrict__ o2)
{
    int row = blockIdx.x, tid = threadIdx.x;        // 256 threads, 2 elems each
    const float* xr = x + (size_t)row * PD;
    float v0 = xr[tid], v1 = xr[tid + 256];
    __shared__ float sred[256];
    sred[tid] = v0*v0 + v1*v1;
    __syncthreads();
    for (int s = 128; s >= 1; s >>= 1) {
        if (tid < s) sred[tid] += sred[tid + s];
        __syncthreads();
    }
    float inv = rsqrtf(sred[0] * (1.0f/512.0f) + 1e-6f);
    size_t base = (size_t)row * PD;
    o1[base + tid]       = v0 * inv * s1[tid];
    o1[base + tid + 256] = v1 * inv * s1[tid + 256];
    if (o2) {
        o2[base + tid]       = v0 * inv * s2[tid];
        o2[base + tid + 256] = v1 * inv * s2[tid + 256];
    }
}

// ---------------- RoPE (in place on q and k) ----------------
__global__ void rope_kernel(float* __restrict__ q, float* __restrict__ k)
{
    int idx = blockIdx.x * blockDim.x + threadIdx.x;
    int row = idx >> 8;
    int p   = idx & 255;          // pair index across heads; col = 2*p
    int i   = p & 31;             // pair within head (DH/2 = 32)
    int t   = row & (PT - 1);
    double freq = exp(-((double)(2*i) / 64.0) * 9.210340371976184);  // 10000^(-2i/64)
    double ang = (double)t * freq;
    float cs = (float)cos(ang);
    float sn = (float)sin(ang);
    size_t off = (size_t)row * PD + 2*p;
    float x0 = q[off], x1 = q[off+1];
    q[off]   = x0*cs - x1*sn;
    q[off+1] = x0*sn + x1*cs;
    x0 = k[off]; x1 = k[off+1];
    k[off]   = x0*cs - x1*sn;
    k[off+1] = x0*sn + x1*cs;
}

// ---------------- causal attention: 1 thread = 1 query row, 32-key tiles ----------------
__global__ void __launch_bounds__(128) attn_kernel(
    const float* __restrict__ q, const float* __restrict__ k,
    const float* __restrict__ v, float* __restrict__ o)
{
    const int BS = 32;
    __shared__ float Ks[BS][64];
    __shared__ float Vs[BS][64];
    int t = blockIdx.x * 128 + threadIdx.x;
    int h = blockIdx.y, b = blockIdx.z;
    const float* qrow = q + ((size_t)(b*PT + t) * PD + h*PDH);
    float qreg[64];
#pragma unroll
    for (int i = 0; i < 64; i++) qreg[i] = qrow[i];
    float m = -1e30f, l = 0.0f;
    float acc[64];
#pragma unroll
    for (int i = 0; i < 64; i++) acc[i] = 0.0f;

    int send = blockIdx.x * 128 + 128;
    for (int s0 = 0; s0 < send; s0 += BS) {
        __syncthreads();
        for (int i = threadIdx.x; i < BS*64/4; i += 128) {
            int rr = i >> 4; int cc = (i & 15) << 2;
            size_t goff = (size_t)(b*PT + s0 + rr) * PD + h*PDH + cc;
            *(float4*)&Ks[rr][cc] = *(const float4*)&k[goff];
            *(float4*)&Vs[rr][cc] = *(const float4*)&v[goff];
        }
        __syncthreads();
        int nval = t - s0 + 1;
        if (nval > BS) nval = BS;
        if (nval > 0) {
            float sc[BS];
            float tm = -1e30f;
#pragma unroll
            for (int j = 0; j < BS; j++) {
                float s = 0.0f;
#pragma unroll
                for (int d = 0; d < 64; d++) s = fmaf(qreg[d], Ks[j][d], s);
                s *= 0.125f;
                sc[j] = (j < nval) ? s : -1e30f;
                tm = fmaxf(tm, sc[j]);
            }
            float nm = fmaxf(m, tm);
            float csc = expf(m - nm);
            l *= csc;
#pragma unroll
            for (int d = 0; d < 64; d++) acc[d] *= csc;
#pragma unroll
            for (int j = 0; j < BS; j++) {
                float p = expf(sc[j] - nm);
                l += p;
#pragma unroll
                for (int d = 0; d < 64; d++) acc[d] = fmaf(p, Vs[j][d], acc[d]);
            }
            m = nm;
        }
    }
    float inv = 1.0f / l;
    float* orow = o + ((size_t)(b*PT + t) * PD + h*PDH);
#pragma unroll
    for (int i = 0; i < 64; i++) orow[i] = acc[i] * inv;
}

// ---------------- silu(g) * val ----------------
__global__ void silu_mul_kernel(const float* __restrict__ gv, float* __restrict__ u)
{
    size_t idx = (size_t)blockIdx.x * blockDim.x + threadIdx.x;  // 16384*2048
    size_t row = idx >> 11;
    int c = (int)(idx & 2047);
    float g  = gv[row*4096 + c];
    float vl = gv[row*4096 + 2048 + c];
    u[idx] = g / (1.0f + expf(-g)) * vl;
}

// ---------------- mean over T (float64 accumulation) ----------------
__global__ void qwin_kernel(const float* __restrict__ h2, double* __restrict__ qwin)
{
    int b = blockIdx.x, d = threadIdx.x;   // 512 threads
    double s = 0.0;
    for (int t = 0; t < PT; t++) s += (double)h2[((size_t)(b*PT + t)) * PD + d];
    qwin[b*PD + d] = s * (1.0 / (double)PT);
}

// ---------------- episodic memory (float64 internals): one block per batch ----------------
__global__ void __launch_bounds__(512) episodic_kernel(
    const float* __restrict__ epi_keys, const float* __restrict__ epi_vals,
    const float* __restrict__ epi_age,  const float* __restrict__ epi_str,
    const float* __restrict__ rms_read,
    const float* __restrict__ Wwk, const float* __restrict__ bwk,
    const float* __restrict__ Wwv, const float* __restrict__ bwv,
    const float* __restrict__ Wws, const float* __restrict__ bws,
    const float* __restrict__ Wg1, const float* __restrict__ bg1,
    const float* __restrict__ Wg2, const float* __restrict__ bg2,
    const double* __restrict__ qwin,
    float* __restrict__ read_out,
    float* __restrict__ keys_new, float* __restrict__ vals_new,
    float* __restrict__ age_new,  float* __restrict__ sn_out,
    float* __restrict__ gate_out)
{
    int b = blockIdx.x;
    int tid = threadIdx.x;          // 512
    int warp = tid >> 5, lane = tid & 31;
    __shared__ double qw[512], wk[512], wv[512], sred[512];
    __shared__ double lg[64], sw[64], wr[64];
    __shared__ double s_qninv, s_ws, s_wkinv, s_best;
    __shared__ int    s_kstar;

    qw[tid] = qwin[b*PD + tid];
    __syncthreads();

    sred[tid] = qw[tid]*qw[tid];
    __syncthreads();
    for (int s = 256; s >= 1; s >>= 1) { if (tid < s) sred[tid] += sred[tid+s]; __syncthreads(); }
    if (tid == 0) s_qninv = 1.0 / (sqrt(sred[0]) + 1e-6);
    __syncthreads();

    double a1 = 0.0, a2 = 0.0;
    for (int i = 0; i < 512; i++) {
        double qv = qw[i];
        a1 += qv * (double)Wwk[i*512 + tid];
        a2 += qv * (double)Wwv[i*512 + tid];
    }
    wk[tid] = a1 + (double)bwk[tid];
    wv[tid] = a2 + (double)bwv[tid];

    sred[tid] = qw[tid] * (double)Wws[tid];
    __syncthreads();
    for (int s = 256; s >= 1; s >>= 1) { if (tid < s) sred[tid] += sred[tid+s]; __syncthreads(); }
    if (tid == 0) s_ws = 1.0 / (1.0 + exp(-(sred[0] + (double)bws[0])));
    __syncthreads();

    sred[tid] = wk[tid]*wk[tid];
    __syncthreads();
    for (int s = 256; s >= 1; s >>= 1) { if (tid < s) sred[tid] += sred[tid+s]; __syncthreads(); }
    if (tid == 0) s_wkinv = 1.0 / (sqrt(sred[0]) + 1e-6);
    __syncthreads();

    for (int kk = warp; kk < PK; kk += 16) {
        const float* kp = epi_keys + (size_t)(b*PK + kk) * PD;
        double ss = 0.0, dq = 0.0, dw = 0.0;
        for (int d = lane; d < 512; d += 32) {
            double kv = (double)kp[d];
            ss += kv * kv;
            dq += kv * qw[d];
            dw += kv * wk[d];
        }
#pragma unroll
        for (int o = 16; o > 0; o >>= 1) {
            ss += __shfl_xor_sync(0xffffffffu, ss, o);
            dq += __shfl_xor_sync(0xffffffffu, dq, o);
            dw += __shfl_xor_sync(0xffffffffu, dw, o);
        }
        if (lane == 0) {
            double kninv = 1.0 / (sqrt(ss) + 1e-6);
            double simr  = dq * kninv * s_qninv;
            double st    = (double)epi_str[b*PK + kk];
            double stc   = fmin(fmax(st, 0.001), 1e9);
            lg[kk] = simr + 0.5*log(stc) - 0.02*(double)epi_age[b*PK + kk]
                   + ((st > 0.001) ? 0.0 : -1000.0);
            sw[kk] = dw * kninv * s_wkinv;
        }
    }
    __syncthreads();

    if (tid == 0) {
        double mx = -1e300;
        for (int kk = 0; kk < PK; kk++) mx = fmax(mx, lg[kk]);
        double sm = 0.0;
        for (int kk = 0; kk < PK; kk++) { double e = exp(lg[kk]-mx); wr[kk] = e; sm += e; }
        double inv = 1.0 / sm;
        for (int kk = 0; kk < PK; kk++) wr[kk] *= inv;
        double bs = -1e300; int kst = 0;
        for (int kk = 0; kk < PK; kk++) if (sw[kk] > bs) { bs = sw[kk]; kst = kk; }
        s_best = bs; s_kstar = kst;
    }
    __syncthreads();

    double r = 0.0;
    for (int kk = 0; kk < PK; kk++)
        r += wr[kk] * (double)epi_vals[(size_t)(b*PK + kk)*PD + tid];
    sred[tid] = r*r;
    __syncthreads();
    for (int s = 256; s >= 1; s >>= 1) { if (tid < s) sred[tid] += sred[tid+s]; __syncthreads(); }
    double rinv = 1.0 / sqrt(sred[0] * (1.0/512.0) + 1e-6);
    read_out[b*PD + tid] = (float)(r * rinv * (double)rms_read[tid]);
    __syncthreads();

    double ws = s_ws; int kstar = s_kstar;

    for (int kk = warp; kk < PK; kk += 16) {
        double re = (kk == kstar) ? ws * 0.5 : 0.0;
        const float* kp = epi_keys + (size_t)(b*PK + kk) * PD;
        const float* vp = epi_vals + (size_t)(b*PK + kk) * PD;
        double ss = 0.0;
        for (int d = lane; d < 512; d += 32) {
            double tk = (1.0 - re)*(double)kp[d] + re*wk[d];
            ss += tk * tk;
            vals_new[(size_t)(b*PK + kk)*PD + d] =
                (float)((1.0 - re)*(double)vp[d] + re*wv[d]);
        }
#pragma unroll
        for (int o = 16; o > 0; o >>= 1) ss += __shfl_xor_sync(0xffffffffu, ss, o);
        double ninv = 1.0 / (sqrt(ss) + 1e-6);
        for (int d = lane; d < 512; d += 32) {
            double tk = (1.0 - re)*(double)kp[d] + re*wk[d];
            keys_new[(size_t)(b*PK + kk)*PD + d] = (float)(tk * ninv);
        }
    }

    if (tid < PK) {
        int kk = tid;
        double ww = (kk == kstar) ? 1.0 : 0.0;
        age_new[b*PK + kk] = (float)(((double)epi_age[b*PK + kk] + 1.0) * (1.0 - ww));
        double s0 = (double)epi_str[b*PK + kk] * 0.995;
        double snv = s0 + ww * ws * (1.0 - s0);
        sn_out[b*PK + kk] = (float)fmin(fmax(snv, 0.001), 1.0);
    }

    double nov = 1.0 - s_best;
    double hsum = (double)bg1[tid];
    for (int i = 0; i < 512; i++) hsum += qw[i] * (double)Wg1[i*512 + tid];
    hsum += ws  * (double)Wg1[512*512 + tid];
    hsum += nov * (double)Wg1[513*512 + tid];
    double sil = hsum / (1.0 + exp(-hsum));
    sred[tid] = sil * (double)Wg2[tid];
    __syncthreads();
    for (int s = 256; s >= 1; s >>= 1) { if (tid < s) sred[tid] += sred[tid+s]; __syncthreads(); }
    if (tid == 0) gate_out[b] = (float)(1.0 / (1.0 + exp(-(sred[0] + (double)bg2[0]))));
}

// ---------------- out += gate[b] * read[b, :] ----------------
__global__ void bcast_add_kernel(float* __restrict__ out,
                                 const float* __restrict__ read,
                                 const float* __restrict__ gate)
{
    size_t idx = (size_t)blockIdx.x * blockDim.x + threadIdx.x;  // 8388608
    int b = (int)(idx >> 18);         // T*D = 262144 per batch
    int d = (int)(idx & 511);
    out[idx] += gate[b] * read[b*PD + d];
}

// ---------------- launch ----------------
extern "C" void kernel_launch(void* const* d_in, const int* in_sizes, int n_in,
                              void* d_out, int out_size)
{
    const float* x        = (const float*)d_in[0];
    const float* epi_keys = (const float*)d_in[1];
    const float* epi_vals = (const float*)d_in[2];
    const float* epi_age  = (const float*)d_in[3];
    const float* epi_str  = (const float*)d_in[4];
    // d_in[5] = pos_idx (arange, implicit)
    const float* rms1     = (const float*)d_in[6];
    const float* rms_kv   = (const float*)d_in[7];
    const float* rms2     = (const float*)d_in[8];
    const float* rms_read = (const float*)d_in[9];
    const float* Wq = (const float*)d_in[10]; const float* bq = (const float*)d_in[11];
    const float* Wk = (const float*)d_in[12]; const float* bk = (const float*)d_in[13];
    const float* Wv = (const float*)d_in[14]; const float* bv = (const float*)d_in[15];
    const float* Wo = (const float*)d_in[16]; const float* bo = (const float*)d_in[17];
    const float* W1 = (const float*)d_in[18]; const float* W2 = (const float*)d_in[19];
    const float* Wwk = (const float*)d_in[20]; const float* bwk = (const float*)d_in[21];
    const float* Wwv = (const float*)d_in[22]; const float* bwv = (const float*)d_in[23];
    const float* Wws = (const float*)d_in[24]; const float* bws = (const float*)d_in[25];
    const float* Wg1 = (const float*)d_in[26]; const float* bg1 = (const float*)d_in[27];
    const float* Wg2 = (const float*)d_in[28]; const float* bg2 = (const float*)d_in[29];

    float *nx, *nkv, *q, *k, *v, *o, *h1, *nh1, *gv, *u, *readb;
    double *qwin;
    cudaGetSymbolAddress((void**)&nx,   g_nx);
    cudaGetSymbolAddress((void**)&nkv,  g_nkv);
    cudaGetSymbolAddress((void**)&q,    g_q);
    cudaGetSymbolAddress((void**)&k,    g_k);
    cudaGetSymbolAddress((void**)&v,    g_v);
    cudaGetSymbolAddress((void**)&o,    g_o);
    cudaGetSymbolAddress((void**)&h1,   g_h1);
    cudaGetSymbolAddress((void**)&nh1,  g_nh1);
    cudaGetSymbolAddress((void**)&gv,   g_gv);
    cudaGetSymbolAddress((void**)&u,    g_u);
    cudaGetSymbolAddress((void**)&qwin, g_qwin);
    cudaGetSymbolAddress((void**)&readb,g_read);

    float* out      = (float*)d_out;
    float* keys_new = out + (size_t)ROWS*PD;                 // 8388608
    float* vals_new = keys_new + (size_t)PB*PK*PD;           // +1048576
    float* age_new  = vals_new + (size_t)PB*PK*PD;           // +1048576
    float* sn       = age_new + PB*PK;                       // +2048
    float* gate     = sn + PB*PK;                            // +2048

    dim3 blk(256);
    dim3 g512(512/128, ROWS/128);    // (4, 128)
    dim3 g4096(4096/128, ROWS/128);  // (32, 128)

    rmsnorm_kernel<<<ROWS, 256>>>(x, rms1, nx, rms_kv, nkv);
    mma_gemm_kernel<true,false><<<g512, blk>>>(nx,  Wq, bq, nullptr, q, ROWS, 512, 512);
    mma_gemm_kernel<true,false><<<g512, blk>>>(nkv, Wk, bk, nullptr, k, ROWS, 512, 512);
    mma_gemm_kernel<true,false><<<g512, blk>>>(nkv, Wv, bv, nullptr, v, ROWS, 512, 512);
    rope_kernel<<<ROWS, 256>>>(q, k);
    attn_kernel<<<dim3(PT/128, PH, PB), 128>>>(q, k, v, o);
    mma_gemm_kernel<true,true><<<g512, blk>>>(o, Wo, bo, x, h1, ROWS, 512, 512);
    rmsnorm_kernel<<<ROWS, 256>>>(h1, rms2, nh1, nullptr, nullptr);
    mma_gemm_kernel<false,false><<<g4096, blk>>>(nh1, W1, nullptr, nullptr, gv, ROWS, 4096, 512);
    silu_mul_kernel<<<(ROWS*2048)/256, 256>>>(gv, u);
    mma_gemm_kernel<false,true><<<g512, blk>>>(u, W2, nullptr, h1, out, ROWS, 512, 2048);
    qwin_kernel<<<PB, 512>>>(out, qwin);
    episodic_kernel<<<PB, 512>>>(epi_keys, epi_vals, epi_age, epi_str, rms_read,
                                 Wwk, bwk, Wwv, bwv, Wws, bws, Wg1, bg1, Wg2, bg2,
                                 qwin, readb, keys_new, vals_new, age_new, sn, gate);
    bcast_add_kernel<<<(ROWS*PD)/256, 256>>>(out, readb, gate);
}